// round 1
// baseline (speedup 1.0000x reference)
#include <cuda_runtime.h>
#include <cuda_bf16.h>
#include <math.h>

#define TT 4096
#define EMB 512
#define HID 2048
#define NCH 256
#define NGATE 4
#define NCOLS 8192            // 4*HID
#define NCTA 128
#define HPB 16                // hidden units per CTA
#define CPB 64                // weight rows per CTA (4 gates * 16)
#define NC 27                 // rows cached in SMEM per CTA
#define THR 1024

// Static device scratch (allocation-free rule: __device__ globals only)
__device__ float g_Wt[(size_t)NCOLS * HID];     // 67 MB: Wt[g*2048+j][k] = Wg[(512+k)*2048+j]
__device__ float g_Zx[(size_t)TT * NCOLS];      // 134 MB: input-part preactivations (+bias)
__device__ float g_hs[(size_t)TT * HID];        // 33.5 MB: hidden states per step
__device__ unsigned g_bar;

__device__ __forceinline__ unsigned ldacq(const unsigned* p) {
    unsigned v;
    asm volatile("ld.acquire.gpu.u32 %0, [%1];" : "=r"(v) : "l"(p) : "memory");
    return v;
}

__global__ void bar_init_kernel() { g_bar = 0u; }

// ---------------------------------------------------------------------------
// K0: transpose hidden-part of gate weights into row-per-output-column layout
// ---------------------------------------------------------------------------
__global__ __launch_bounds__(256) void wt_transpose_kernel(
    const float* __restrict__ W0, const float* __restrict__ W1,
    const float* __restrict__ W2, const float* __restrict__ W3)
{
    __shared__ float tile[32][33];
    int g = blockIdx.z;
    const float* W = (g == 0) ? W0 : (g == 1) ? W1 : (g == 2) ? W2 : W3;
    int k0 = blockIdx.x * 32;
    int j0 = blockIdx.y * 32;
    int tx = threadIdx.x & 31;
    int ty = threadIdx.x >> 5;   // 0..7

#pragma unroll
    for (int i = 0; i < 4; ++i) {
        int r = ty + i * 8;
        tile[r][tx] = W[(size_t)(EMB + k0 + r) * HID + (j0 + tx)];
    }
    __syncthreads();
#pragma unroll
    for (int i = 0; i < 4; ++i) {
        int r = ty + i * 8;
        g_Wt[((size_t)g * HID + (j0 + r)) * HID + (k0 + tx)] = tile[tx][r];
    }
}

// ---------------------------------------------------------------------------
// K1: Zx[t][g*2048+j] = sum_k emb[idx[t]][k] * Wg[k][j] + bg[j]
//     GEMM M=4096, N=8192, K=512; 64x64 tiles, 256 threads, 4x4 per thread
// ---------------------------------------------------------------------------
__global__ __launch_bounds__(256) void zx_gemm_kernel(
    const int* __restrict__ idx, const float* __restrict__ emb,
    const float* __restrict__ W0, const float* __restrict__ W1,
    const float* __restrict__ W2, const float* __restrict__ W3,
    const float* __restrict__ b0, const float* __restrict__ b1,
    const float* __restrict__ b2, const float* __restrict__ b3)
{
    __shared__ float As[64][17];
    __shared__ float Bs[16][64];
    __shared__ int idx_s[64];

    int m0 = blockIdx.x * 64;
    int n0 = blockIdx.y * 64;
    int gate = n0 >> 11;
    int j0 = n0 & (HID - 1);
    const float* W = (gate == 0) ? W0 : (gate == 1) ? W1 : (gate == 2) ? W2 : W3;
    const float* bias = (gate == 0) ? b0 : (gate == 1) ? b1 : (gate == 2) ? b2 : b3;

    int tid = threadIdx.x;
    int tx = tid & 15, ty = tid >> 4;

    if (tid < 64) idx_s[tid] = idx[m0 + tid];
    __syncthreads();

    float acc[4][4] = {};
    for (int k0 = 0; k0 < EMB; k0 += 16) {
        {
            int kk = tid & 15;
            int mmb = tid >> 4;
#pragma unroll
            for (int r = 0; r < 4; ++r) {
                int mm = mmb + r * 16;
                As[mm][kk] = emb[(size_t)idx_s[mm] * EMB + k0 + kk];
            }
        }
        {
            int nn = tid & 63;
            int kkb = tid >> 6;
#pragma unroll
            for (int r = 0; r < 4; ++r) {
                int kk = kkb + r * 4;
                Bs[kk][nn] = W[(size_t)(k0 + kk) * HID + j0 + nn];
            }
        }
        __syncthreads();
#pragma unroll
        for (int kk = 0; kk < 16; ++kk) {
            float a[4];
#pragma unroll
            for (int i = 0; i < 4; ++i) a[i] = As[ty * 4 + i][kk];
            float4 bv = *(const float4*)&Bs[kk][tx * 4];
            float b[4] = {bv.x, bv.y, bv.z, bv.w};
#pragma unroll
            for (int i = 0; i < 4; ++i)
#pragma unroll
                for (int j = 0; j < 4; ++j) acc[i][j] += a[i] * b[j];
        }
        __syncthreads();
    }
#pragma unroll
    for (int i = 0; i < 4; ++i) {
        int m = m0 + ty * 4 + i;
#pragma unroll
        for (int j = 0; j < 4; ++j) {
            int n = n0 + tx * 4 + j;
            g_Zx[(size_t)m * NCOLS + n] = acc[i][j] + bias[j0 + tx * 4 + j];
        }
    }
}

// ---------------------------------------------------------------------------
// K2: persistent recurrent LSTM. 128 CTAs, 1024 threads, 1 CTA/SM.
// Each CTA owns 16 hidden units (all 4 gates). 27 of its 64 weight rows are
// pinned in SMEM; the rest stream from L2 every step. Grid barrier per step.
// ---------------------------------------------------------------------------
#define SMEM_FLOATS (HID + NC * HID + CPB + HPB)
#define SMEM_BYTES (SMEM_FLOATS * 4)

__global__ __launch_bounds__(THR, 1) void lstm_seq_kernel(
    const float* __restrict__ hidden0, const float* __restrict__ cell0,
    float* __restrict__ dout)
{
    extern __shared__ float smem[];
    float* h_sh = smem;                 // [2048]
    float* wc   = smem + HID;           // [NC][2048]
    float* zbuf = wc + NC * HID;        // [64]
    float* c_sh = zbuf + CPB;           // [16]

    const int cta = blockIdx.x;
    const int tid = threadIdx.x;
    const int col = tid >> 4;           // 0..63 local weight row
    const int sub = tid & 15;           // 0..15 k-slice
    const int hid0 = cta * HPB;

    const int g  = col >> 4;            // gate of this column
    const int jl = col & 15;            // local hidden index
    const int row = g * HID + hid0 + jl;
    const float* wrow_g = g_Wt + (size_t)row * HID;
    const bool cached = (col < NC);

    // fill SMEM weight cache (rows 0..NC-1 in local enumeration)
    for (int rr = 0; rr < NC; ++rr) {
        int gg = rr >> 4, jj = rr & 15;
        const float* src = g_Wt + ((size_t)gg * HID + hid0 + jj) * HID;
        for (int k = tid; k < HID; k += THR) wc[rr * HID + k] = src[k];
    }
    if (tid < HPB) c_sh[tid] = cell0[hid0 + tid];
    __syncthreads();

    const float4* wc4 = (const float4*)(wc + col * HID);
    const float4* wg4 = (const float4*)wrow_g;
    const float4* h4  = (const float4*)h_sh;

    for (int t = 0; t < TT; ++t) {
        // load h_{t-1} into SMEM
        const float* hprev = (t == 0) ? hidden0 : (g_hs + (size_t)(t - 1) * HID);
        for (int k = tid; k < HID; k += THR) h_sh[k] = hprev[k];

        // prefetch Zx for this step (overlaps matvec)
        float zx0 = 0.f, zx1 = 0.f, zx2 = 0.f, zx3 = 0.f;
        if (tid < HPB) {
            const float* zp = g_Zx + (size_t)t * NCOLS + hid0 + tid;
            zx0 = zp[0];
            zx1 = zp[HID];
            zx2 = zp[2 * HID];
            zx3 = zp[3 * HID];
        }
        __syncthreads();

        // matvec: this thread covers k = q*64 + sub*4 (q=0..31) of its column
        float acc = 0.f;
        if (cached) {
#pragma unroll 8
            for (int q = 0; q < 32; ++q) {
                int i4 = q * 16 + sub;
                float4 w = wc4[i4];
                float4 h = h4[i4];
                acc += w.x * h.x + w.y * h.y + w.z * h.z + w.w * h.w;
            }
        } else {
#pragma unroll 8
            for (int q = 0; q < 32; ++q) {
                int i4 = q * 16 + sub;
                float4 w = __ldg(wg4 + i4);
                float4 h = h4[i4];
                acc += w.x * h.x + w.y * h.y + w.z * h.z + w.w * h.w;
            }
        }
        // reduce 16 partials within half-warp
#pragma unroll
        for (int off = 8; off; off >>= 1)
            acc += __shfl_down_sync(0xffffffffu, acc, off, 16);
        if (sub == 0) zbuf[col] = acc;
        __syncthreads();

        // gate combine for this CTA's 16 hidden units
        if (tid < HPB) {
            int j = tid;
            float zf = zbuf[j]      + zx0;
            float zi = zbuf[16 + j] + zx1;
            float zo = zbuf[32 + j] + zx2;
            float zc = zbuf[48 + j] + zx3;
            float f = 1.0f / (1.0f + expf(-zf));
            float i_ = 1.0f / (1.0f + expf(-zi));
            float o_ = 1.0f / (1.0f + expf(-zo));
            float gg = tanhf(zc);
            float cn = f * c_sh[j] + i_ * gg;
            c_sh[j] = cn;
            float hn = o_ * tanhf(cn);
            g_hs[(size_t)t * HID + hid0 + j] = hn;
            if (t == TT - 1) {
                dout[(size_t)TT * NCH + hid0 + j] = hn;          // h_fin
                dout[(size_t)TT * NCH + HID + hid0 + j] = cn;    // c_fin
            }
        }
        __syncthreads();

        // grid barrier (all 128 CTAs co-resident, 1 per SM)
        if (tid == 0) {
            __threadfence();
            atomicAdd(&g_bar, 1u);
            unsigned target = (unsigned)(t + 1) * gridDim.x;
            while (ldacq(&g_bar) < target) { __nanosleep(64); }
        }
        __syncthreads();
    }
}

// ---------------------------------------------------------------------------
// K3: out[t][n] = hs[t] @ Wout + bout.  M=4096, N=256, K=2048
// ---------------------------------------------------------------------------
__global__ __launch_bounds__(256) void out_gemm_kernel(
    const float* __restrict__ Wout, const float* __restrict__ bout,
    float* __restrict__ dout)
{
    __shared__ float As[64][17];
    __shared__ float Bs[16][64];

    int m0 = blockIdx.x * 64;
    int n0 = blockIdx.y * 64;
    int tid = threadIdx.x;
    int tx = tid & 15, ty = tid >> 4;

    float acc[4][4] = {};
    for (int k0 = 0; k0 < HID; k0 += 16) {
        {
            int kk = tid & 15;
            int mmb = tid >> 4;
#pragma unroll
            for (int r = 0; r < 4; ++r) {
                int mm = mmb + r * 16;
                As[mm][kk] = g_hs[(size_t)(m0 + mm) * HID + k0 + kk];
            }
        }
        {
            int nn = tid & 63;
            int kkb = tid >> 6;
#pragma unroll
            for (int r = 0; r < 4; ++r) {
                int kk = kkb + r * 4;
                Bs[kk][nn] = Wout[(size_t)(k0 + kk) * NCH + n0 + nn];
            }
        }
        __syncthreads();
#pragma unroll
        for (int kk = 0; kk < 16; ++kk) {
            float a[4];
#pragma unroll
            for (int i = 0; i < 4; ++i) a[i] = As[ty * 4 + i][kk];
            float4 bv = *(const float4*)&Bs[kk][tx * 4];
            float b[4] = {bv.x, bv.y, bv.z, bv.w};
#pragma unroll
            for (int i = 0; i < 4; ++i)
#pragma unroll
                for (int j = 0; j < 4; ++j) acc[i][j] += a[i] * b[j];
        }
        __syncthreads();
    }
#pragma unroll
    for (int i = 0; i < 4; ++i) {
        int m = m0 + ty * 4 + i;
#pragma unroll
        for (int j = 0; j < 4; ++j) {
            int n = n0 + tx * 4 + j;
            dout[(size_t)m * NCH + n] = acc[i][j] + bout[n];
        }
    }
}

// ---------------------------------------------------------------------------
extern "C" void kernel_launch(void* const* d_in, const int* in_sizes, int n_in,
                              void* d_out, int out_size)
{
    const int*   idx    = (const int*)d_in[0];
    const float* hidden = (const float*)d_in[1];
    const float* cell   = (const float*)d_in[2];
    const float* emb    = (const float*)d_in[3];
    const float* Wf     = (const float*)d_in[4];
    const float* bf     = (const float*)d_in[5];
    const float* Wi     = (const float*)d_in[6];
    const float* bi     = (const float*)d_in[7];
    const float* Wo     = (const float*)d_in[8];
    const float* bo     = (const float*)d_in[9];
    const float* Wc     = (const float*)d_in[10];
    const float* bc     = (const float*)d_in[11];
    const float* Wout   = (const float*)d_in[12];
    const float* bout   = (const float*)d_in[13];
    float* out = (float*)d_out;

    // idempotent; already effective from the correctness call before capture
    cudaFuncSetAttribute(lstm_seq_kernel,
                         cudaFuncAttributeMaxDynamicSharedMemorySize, SMEM_BYTES);

    bar_init_kernel<<<1, 1>>>();
    wt_transpose_kernel<<<dim3(64, 64, 4), 256>>>(Wf, Wi, Wo, Wc);
    zx_gemm_kernel<<<dim3(64, 128), 256>>>(idx, emb, Wf, Wi, Wo, Wc, bf, bi, bo, bc);
    lstm_seq_kernel<<<NCTA, THR, SMEM_BYTES>>>(hidden, cell, out);
    out_gemm_kernel<<<dim3(64, 4), 256>>>(Wout, bout, out);
}

// round 2
// speedup vs baseline: 1.2224x; 1.2224x over previous
#include <cuda_runtime.h>
#include <cuda_bf16.h>
#include <math.h>

#define TT 4096
#define EMB 512
#define HID 2048
#define NCH 256
#define NCOLS 8192            // 4*HID
#define NCTA 128
#define HPB 16                // hidden units per CTA
#define THR 1024
#define NC 27                 // weight rows cached in SMEM per CTA (of 64)
#define G1 11                 // gate-1 rows cached for g < G1 (16 + 11 = 27)

// Static device scratch (allocation-free rule: __device__ globals only)
__device__ float g_Wt[(size_t)NCOLS * HID];     // Wt[gate*2048+j][k] = Wg[(512+k)*2048+j]
__device__ float g_Zx[(size_t)TT * NCOLS];      // input-part preactivations (+bias)
__device__ float g_hs[(size_t)TT * HID];        // hidden states per step
__device__ unsigned g_bar;

__device__ __forceinline__ unsigned ldacq(const unsigned* p) {
    unsigned v;
    asm volatile("ld.acquire.gpu.u32 %0, [%1];" : "=r"(v) : "l"(p) : "memory");
    return v;
}

__global__ void bar_init_kernel() { g_bar = 0u; }

// ---------------------------------------------------------------------------
// K0: transpose hidden-part of gate weights into row-per-output-column layout
// ---------------------------------------------------------------------------
__global__ __launch_bounds__(256) void wt_transpose_kernel(
    const float* __restrict__ W0, const float* __restrict__ W1,
    const float* __restrict__ W2, const float* __restrict__ W3)
{
    __shared__ float tile[32][33];
    int g = blockIdx.z;
    const float* W = (g == 0) ? W0 : (g == 1) ? W1 : (g == 2) ? W2 : W3;
    int k0 = blockIdx.x * 32;
    int j0 = blockIdx.y * 32;
    int tx = threadIdx.x & 31;
    int ty = threadIdx.x >> 5;

#pragma unroll
    for (int i = 0; i < 4; ++i) {
        int r = ty + i * 8;
        tile[r][tx] = W[(size_t)(EMB + k0 + r) * HID + (j0 + tx)];
    }
    __syncthreads();
#pragma unroll
    for (int i = 0; i < 4; ++i) {
        int r = ty + i * 8;
        g_Wt[((size_t)g * HID + (j0 + r)) * HID + (k0 + tx)] = tile[tx][r];
    }
}

// ---------------------------------------------------------------------------
// K1: Zx[t][g*2048+j] = emb[idx[t]] @ Wg[:512] + bg   (M=4096,N=8192,K=512)
// ---------------------------------------------------------------------------
__global__ __launch_bounds__(256) void zx_gemm_kernel(
    const int* __restrict__ idx, const float* __restrict__ emb,
    const float* __restrict__ W0, const float* __restrict__ W1,
    const float* __restrict__ W2, const float* __restrict__ W3,
    const float* __restrict__ b0, const float* __restrict__ b1,
    const float* __restrict__ b2, const float* __restrict__ b3)
{
    __shared__ float As[64][17];
    __shared__ float Bs[16][64];
    __shared__ int idx_s[64];

    int m0 = blockIdx.x * 64;
    int n0 = blockIdx.y * 64;
    int gate = n0 >> 11;
    int j0 = n0 & (HID - 1);
    const float* W = (gate == 0) ? W0 : (gate == 1) ? W1 : (gate == 2) ? W2 : W3;
    const float* bias = (gate == 0) ? b0 : (gate == 1) ? b1 : (gate == 2) ? b2 : b3;

    int tid = threadIdx.x;
    int tx = tid & 15, ty = tid >> 4;

    if (tid < 64) idx_s[tid] = idx[m0 + tid];
    __syncthreads();

    float acc[4][4] = {};
    for (int k0 = 0; k0 < EMB; k0 += 16) {
        {
            int kk = tid & 15;
            int mmb = tid >> 4;
#pragma unroll
            for (int r = 0; r < 4; ++r) {
                int mm = mmb + r * 16;
                As[mm][kk] = emb[(size_t)idx_s[mm] * EMB + k0 + kk];
            }
        }
        {
            int nn = tid & 63;
            int kkb = tid >> 6;
#pragma unroll
            for (int r = 0; r < 4; ++r) {
                int kk = kkb + r * 4;
                Bs[kk][nn] = W[(size_t)(k0 + kk) * HID + j0 + nn];
            }
        }
        __syncthreads();
#pragma unroll
        for (int kk = 0; kk < 16; ++kk) {
            float a[4];
#pragma unroll
            for (int i = 0; i < 4; ++i) a[i] = As[ty * 4 + i][kk];
            float4 bv = *(const float4*)&Bs[kk][tx * 4];
            float b[4] = {bv.x, bv.y, bv.z, bv.w};
#pragma unroll
            for (int i = 0; i < 4; ++i)
#pragma unroll
                for (int j = 0; j < 4; ++j) acc[i][j] += a[i] * b[j];
        }
        __syncthreads();
    }
#pragma unroll
    for (int i = 0; i < 4; ++i) {
        int m = m0 + ty * 4 + i;
#pragma unroll
        for (int j = 0; j < 4; ++j) {
            int n = n0 + tx * 4 + j;
            g_Zx[(size_t)m * NCOLS + n] = acc[i][j] + bias[j0 + tx * 4 + j];
        }
    }
}

// ---------------------------------------------------------------------------
// K2: persistent recurrent LSTM, register-blocked GEMV.
// 128 CTAs x 1024 threads. Group g (64 threads = 2 warps) owns hidden unit
// hid0+g: all 4 gate rows. Each thread covers a 32-float k-slice of all 4
// rows, so each h float4 is read from SMEM once and reused 4x.
// SMEM caches 27 of the 64 weight rows (gate0 all 16, gate1 for g<11);
// gates 2,3 (+gate1 g>=11) stream from L2 each step.
// ---------------------------------------------------------------------------
#define SMEM_FLOATS (HID + NC * HID + 128 + HPB)
#define SMEM_BYTES (SMEM_FLOATS * 4)

__global__ __launch_bounds__(THR, 1) void lstm_seq_kernel(
    const float* __restrict__ hidden0, const float* __restrict__ cell0,
    float* __restrict__ dout)
{
    extern __shared__ float smem[];
    float* h_sh = smem;                 // [2048]
    float* wc   = smem + HID;           // [NC][2048]
    float* zbuf = wc + NC * HID;        // [16][2][4]
    float* c_sh = zbuf + 128;           // [16]

    const int cta = blockIdx.x;
    const int tid = threadIdx.x;
    const int g    = tid >> 6;          // 0..15: hidden unit within CTA
    const int slice = tid & 63;         // 0..63: k-slice (8 float4, stride 64)
    const int half = (tid >> 5) & 1;    // warp within group
    const int hid0 = cta * HPB;

    // SMEM slots: slot g       -> gate0 row of unit g
    //             slot 16+g    -> gate1 row of unit g (only g < G1)
    // fill SMEM weight cache
    for (int slot = 0; slot < NC; ++slot) {
        int gate = (slot < 16) ? 0 : 1;
        int j    = (slot < 16) ? slot : (slot - 16);
        const float* src = g_Wt + ((size_t)gate * HID + hid0 + j) * HID;
        for (int k = tid; k < HID; k += THR) wc[slot * HID + k] = src[k];
    }
    if (tid < HPB) c_sh[tid] = cell0[hid0 + tid];
    __syncthreads();

    const bool g1_smem = (g < G1);
    const float4* w0p = (const float4*)(wc + g * HID);
    const float4* w1p = g1_smem ? (const float4*)(wc + (16 + g) * HID)
                                : (const float4*)(g_Wt + ((size_t)1 * HID + hid0 + g) * HID);
    const float4* w2p = (const float4*)(g_Wt + ((size_t)2 * HID + hid0 + g) * HID);
    const float4* w3p = (const float4*)(g_Wt + ((size_t)3 * HID + hid0 + g) * HID);
    const float4* h4  = (const float4*)h_sh;

    for (int t = 0; t < TT; ++t) {
        // prefetch Zx for this step (independent of h)
        float zx0 = 0.f, zx1 = 0.f, zx2 = 0.f, zx3 = 0.f;
        if (tid < HPB) {
            const float* zp = g_Zx + (size_t)t * NCOLS + hid0 + tid;
            zx0 = zp[0];
            zx1 = zp[HID];
            zx2 = zp[2 * HID];
            zx3 = zp[3 * HID];
        }

        // load h_{t-1} into SMEM
        const float* hprev = (t == 0) ? hidden0 : (g_hs + (size_t)(t - 1) * HID);
        h_sh[tid] = hprev[tid];
        h_sh[tid + THR] = hprev[tid + THR];
        __syncthreads();

        // register-blocked matvec: 4 gate rows of unit g, k-slice of 8 float4
        float a0 = 0.f, a1 = 0.f, a2 = 0.f, a3 = 0.f;
#pragma unroll 4
        for (int i = 0; i < 8; ++i) {
            int i4 = i * 64 + slice;
            float4 w2 = __ldg(w2p + i4);
            float4 w3 = __ldg(w3p + i4);
            float4 w1 = g1_smem ? w1p[i4] : __ldg(w1p + i4);
            float4 w0 = w0p[i4];
            float4 hv = h4[i4];
            a0 += w0.x * hv.x + w0.y * hv.y + w0.z * hv.z + w0.w * hv.w;
            a1 += w1.x * hv.x + w1.y * hv.y + w1.z * hv.z + w1.w * hv.w;
            a2 += w2.x * hv.x + w2.y * hv.y + w2.z * hv.z + w2.w * hv.w;
            a3 += w3.x * hv.x + w3.y * hv.y + w3.z * hv.z + w3.w * hv.w;
        }
        // warp reduction (each group = 2 full warps)
#pragma unroll
        for (int off = 16; off; off >>= 1) {
            a0 += __shfl_down_sync(0xffffffffu, a0, off);
            a1 += __shfl_down_sync(0xffffffffu, a1, off);
            a2 += __shfl_down_sync(0xffffffffu, a2, off);
            a3 += __shfl_down_sync(0xffffffffu, a3, off);
        }
        if ((tid & 31) == 0) {
            float* zb = zbuf + g * 8 + half * 4;
            zb[0] = a0; zb[1] = a1; zb[2] = a2; zb[3] = a3;
        }
        __syncthreads();

        // gate combine for this CTA's 16 hidden units
        if (tid < HPB) {
            int j = tid;
            const float* zb = zbuf + j * 8;
            float zf = zb[0] + zb[4] + zx0;
            float zi = zb[1] + zb[5] + zx1;
            float zo = zb[2] + zb[6] + zx2;
            float zc = zb[3] + zb[7] + zx3;
            float f  = 1.0f / (1.0f + expf(-zf));
            float i_ = 1.0f / (1.0f + expf(-zi));
            float o_ = 1.0f / (1.0f + expf(-zo));
            float gg = tanhf(zc);
            float cn = f * c_sh[j] + i_ * gg;
            c_sh[j] = cn;
            float hn = o_ * tanhf(cn);
            g_hs[(size_t)t * HID + hid0 + j] = hn;
            if (t == TT - 1) {
                dout[(size_t)TT * NCH + hid0 + j] = hn;          // h_fin
                dout[(size_t)TT * NCH + HID + hid0 + j] = cn;    // c_fin
            }
        }
        __syncthreads();

        // grid barrier (128 CTAs co-resident, 1/SM)
        if (tid == 0) {
            __threadfence();
            asm volatile("red.release.gpu.global.add.u32 [%0], %1;"
                         :: "l"(&g_bar), "r"(1u) : "memory");
            unsigned target = (unsigned)(t + 1) * gridDim.x;
            while (ldacq(&g_bar) < target) { __nanosleep(32); }
        }
        __syncthreads();
    }
}

// ---------------------------------------------------------------------------
// K3: out[t][n] = hs[t] @ Wout + bout.  M=4096, N=256, K=2048
// ---------------------------------------------------------------------------
__global__ __launch_bounds__(256) void out_gemm_kernel(
    const float* __restrict__ Wout, const float* __restrict__ bout,
    float* __restrict__ dout)
{
    __shared__ float As[64][17];
    __shared__ float Bs[16][64];

    int m0 = blockIdx.x * 64;
    int n0 = blockIdx.y * 64;
    int tid = threadIdx.x;
    int tx = tid & 15, ty = tid >> 4;

    float acc[4][4] = {};
    for (int k0 = 0; k0 < HID; k0 += 16) {
        {
            int kk = tid & 15;
            int mmb = tid >> 4;
#pragma unroll
            for (int r = 0; r < 4; ++r) {
                int mm = mmb + r * 16;
                As[mm][kk] = g_hs[(size_t)(m0 + mm) * HID + k0 + kk];
            }
        }
        {
            int nn = tid & 63;
            int kkb = tid >> 6;
#pragma unroll
            for (int r = 0; r < 4; ++r) {
                int kk = kkb + r * 4;
                Bs[kk][nn] = Wout[(size_t)(k0 + kk) * NCH + n0 + nn];
            }
        }
        __syncthreads();
#pragma unroll
        for (int kk = 0; kk < 16; ++kk) {
            float a[4];
#pragma unroll
            for (int i = 0; i < 4; ++i) a[i] = As[ty * 4 + i][kk];
            float4 bv = *(const float4*)&Bs[kk][tx * 4];
            float b[4] = {bv.x, bv.y, bv.z, bv.w};
#pragma unroll
            for (int i = 0; i < 4; ++i)
#pragma unroll
                for (int j = 0; j < 4; ++j) acc[i][j] += a[i] * b[j];
        }
        __syncthreads();
    }
#pragma unroll
    for (int i = 0; i < 4; ++i) {
        int m = m0 + ty * 4 + i;
#pragma unroll
        for (int j = 0; j < 4; ++j) {
            int n = n0 + tx * 4 + j;
            dout[(size_t)m * NCH + n] = acc[i][j] + bout[n];
        }
    }
}

// ---------------------------------------------------------------------------
extern "C" void kernel_launch(void* const* d_in, const int* in_sizes, int n_in,
                              void* d_out, int out_size)
{
    const int*   idx    = (const int*)d_in[0];
    const float* hidden = (const float*)d_in[1];
    const float* cell   = (const float*)d_in[2];
    const float* emb    = (const float*)d_in[3];
    const float* Wf     = (const float*)d_in[4];
    const float* bf     = (const float*)d_in[5];
    const float* Wi     = (const float*)d_in[6];
    const float* bi     = (const float*)d_in[7];
    const float* Wo     = (const float*)d_in[8];
    const float* bo     = (const float*)d_in[9];
    const float* Wc     = (const float*)d_in[10];
    const float* bc     = (const float*)d_in[11];
    const float* Wout   = (const float*)d_in[12];
    const float* bout   = (const float*)d_in[13];
    float* out = (float*)d_out;

    cudaFuncSetAttribute(lstm_seq_kernel,
                         cudaFuncAttributeMaxDynamicSharedMemorySize, SMEM_BYTES);

    bar_init_kernel<<<1, 1>>>();
    wt_transpose_kernel<<<dim3(64, 64, 4), 256>>>(Wf, Wi, Wo, Wc);
    zx_gemm_kernel<<<dim3(64, 128), 256>>>(idx, emb, Wf, Wi, Wo, Wc, bf, bi, bo, bc);
    lstm_seq_kernel<<<NCTA, THR, SMEM_BYTES>>>(hidden, cell, out);
    out_gemm_kernel<<<dim3(64, 4), 256>>>(Wout, bout, out);
}

// round 3
// speedup vs baseline: 1.3174x; 1.0777x over previous
#include <cuda_runtime.h>
#include <cuda_bf16.h>
#include <math.h>

#define TT 4096
#define EMB 512
#define HID 2048
#define NCH 256
#define NCOLS 8192            // 4*HID
#define NCTA 128
#define HPB 16                // hidden units per CTA (one warp each)
#define THR 512               // 16 warps
#define NC 27                 // weight rows cached in SMEM per CTA (of 64)
#define G1 11                 // gate-1 rows cached for unit w < G1

// Static device scratch (allocation-free rule: __device__ globals only)
__device__ float g_Wt[(size_t)NCOLS * HID];     // Wt[gate*2048+j][k] = Wg[(512+k)*2048+j]
__device__ float g_Zx[(size_t)TT * NCOLS];      // input-part preactivations (+bias)
__device__ float g_hs[(size_t)TT * HID];        // hidden states per step
__device__ unsigned g_bar;

__device__ __forceinline__ unsigned ldacq(const unsigned* p) {
    unsigned v;
    asm volatile("ld.acquire.gpu.u32 %0, [%1];" : "=r"(v) : "l"(p) : "memory");
    return v;
}

__global__ void bar_init_kernel() { g_bar = 0u; }

// ---------------------------------------------------------------------------
// K0: transpose hidden-part of gate weights into row-per-output-column layout
// ---------------------------------------------------------------------------
__global__ __launch_bounds__(256) void wt_transpose_kernel(
    const float* __restrict__ W0, const float* __restrict__ W1,
    const float* __restrict__ W2, const float* __restrict__ W3)
{
    __shared__ float tile[32][33];
    int g = blockIdx.z;
    const float* W = (g == 0) ? W0 : (g == 1) ? W1 : (g == 2) ? W2 : W3;
    int k0 = blockIdx.x * 32;
    int j0 = blockIdx.y * 32;
    int tx = threadIdx.x & 31;
    int ty = threadIdx.x >> 5;

#pragma unroll
    for (int i = 0; i < 4; ++i) {
        int r = ty + i * 8;
        tile[r][tx] = W[(size_t)(EMB + k0 + r) * HID + (j0 + tx)];
    }
    __syncthreads();
#pragma unroll
    for (int i = 0; i < 4; ++i) {
        int r = ty + i * 8;
        g_Wt[((size_t)g * HID + (j0 + r)) * HID + (k0 + tx)] = tile[tx][r];
    }
}

// ---------------------------------------------------------------------------
// K1: Zx[t][g*2048+j] = emb[idx[t]] @ Wg[:512] + bg   (M=4096,N=8192,K=512)
// ---------------------------------------------------------------------------
__global__ __launch_bounds__(256) void zx_gemm_kernel(
    const int* __restrict__ idx, const float* __restrict__ emb,
    const float* __restrict__ W0, const float* __restrict__ W1,
    const float* __restrict__ W2, const float* __restrict__ W3,
    const float* __restrict__ b0, const float* __restrict__ b1,
    const float* __restrict__ b2, const float* __restrict__ b3)
{
    __shared__ float As[64][17];
    __shared__ float Bs[16][64];
    __shared__ int idx_s[64];

    int m0 = blockIdx.x * 64;
    int n0 = blockIdx.y * 64;
    int gate = n0 >> 11;
    int j0 = n0 & (HID - 1);
    const float* W = (gate == 0) ? W0 : (gate == 1) ? W1 : (gate == 2) ? W2 : W3;
    const float* bias = (gate == 0) ? b0 : (gate == 1) ? b1 : (gate == 2) ? b2 : b3;

    int tid = threadIdx.x;
    int tx = tid & 15, ty = tid >> 4;

    if (tid < 64) idx_s[tid] = idx[m0 + tid];
    __syncthreads();

    float acc[4][4] = {};
    for (int k0 = 0; k0 < EMB; k0 += 16) {
        {
            int kk = tid & 15;
            int mmb = tid >> 4;
#pragma unroll
            for (int r = 0; r < 4; ++r) {
                int mm = mmb + r * 16;
                As[mm][kk] = emb[(size_t)idx_s[mm] * EMB + k0 + kk];
            }
        }
        {
            int nn = tid & 63;
            int kkb = tid >> 6;
#pragma unroll
            for (int r = 0; r < 4; ++r) {
                int kk = kkb + r * 4;
                Bs[kk][nn] = W[(size_t)(k0 + kk) * HID + j0 + nn];
            }
        }
        __syncthreads();
#pragma unroll
        for (int kk = 0; kk < 16; ++kk) {
            float a[4];
#pragma unroll
            for (int i = 0; i < 4; ++i) a[i] = As[ty * 4 + i][kk];
            float4 bv = *(const float4*)&Bs[kk][tx * 4];
            float b[4] = {bv.x, bv.y, bv.z, bv.w};
#pragma unroll
            for (int i = 0; i < 4; ++i)
#pragma unroll
                for (int j = 0; j < 4; ++j) acc[i][j] += a[i] * b[j];
        }
        __syncthreads();
    }
#pragma unroll
    for (int i = 0; i < 4; ++i) {
        int m = m0 + ty * 4 + i;
#pragma unroll
        for (int j = 0; j < 4; ++j) {
            int n = n0 + tx * 4 + j;
            g_Zx[(size_t)m * NCOLS + n] = acc[i][j] + bias[j0 + tx * 4 + j];
        }
    }
}

// ---------------------------------------------------------------------------
// K2: persistent recurrent LSTM, warp-per-unit, RF+SMEM-pinned weights.
// 128 CTAs x 512 threads (16 warps, 128 regs/thread = full RF).
// Warp w owns hidden unit hid0+w: all 4 gate rows. Lane l covers k-slices
// i*128+l*4 (i=0..15, float4). Gate-3 row slice lives in registers (64 regs),
// gate-0 (all 16) + gate-1 (units 0..10) rows live in SMEM; gate-2 and
// remaining gate-1 rows stream from L2 each step (21 rows * 8KB).
// ---------------------------------------------------------------------------
#define SMEM_FLOATS (HID + NC * HID)
#define SMEM_BYTES (SMEM_FLOATS * 4)

__global__ __launch_bounds__(THR, 1) void lstm_seq_kernel(
    const float* __restrict__ hidden0, const float* __restrict__ cell0,
    float* __restrict__ dout)
{
    extern __shared__ float smem[];
    float* h_sh = smem;                 // [2048]
    float* wc   = smem + HID;           // [NC][2048]

    const int cta  = blockIdx.x;
    const int tid  = threadIdx.x;
    const int w    = tid >> 5;          // warp = hidden unit index within CTA
    const int lane = tid & 31;
    const int hid0 = cta * HPB;

    // fill SMEM weight cache: slot w = gate0 row of unit w; slot 16+w = gate1
    for (int slot = 0; slot < NC; ++slot) {
        int gate = (slot < 16) ? 0 : 1;
        int j    = (slot < 16) ? slot : (slot - 16);
        const float* src = g_Wt + ((size_t)gate * HID + hid0 + j) * HID;
        for (int k = tid; k < HID; k += THR) wc[slot * HID + k] = src[k];
    }

    // pin gate-3 row slice in registers: 16 float4 per lane
    const float4* w3g = (const float4*)(g_Wt + ((size_t)3 * HID + hid0 + w) * HID);
    float4 w3r[16];
#pragma unroll
    for (int i = 0; i < 16; ++i) w3r[i] = w3g[i * 32 + lane];

    float c = 0.f;
    if (lane == 0) c = cell0[hid0 + w];
    __syncthreads();

    const bool g1_smem = (w < G1);
    const float4* w0p = (const float4*)(wc + w * HID);
    const float4* w1p = g1_smem ? (const float4*)(wc + (16 + w) * HID)
                                : (const float4*)(g_Wt + ((size_t)1 * HID + hid0 + w) * HID);
    const float4* w2p = (const float4*)(g_Wt + ((size_t)2 * HID + hid0 + w) * HID);
    const float4* h4  = (const float4*)h_sh;
    float4* h4s = (float4*)h_sh;

    for (int t = 0; t < TT; ++t) {
        // prefetch Zx for this step (independent of h)
        float zx0 = 0.f, zx1 = 0.f, zx2 = 0.f, zx3 = 0.f;
        if (lane == 0) {
            const float* zp = g_Zx + (size_t)t * NCOLS + hid0 + w;
            zx0 = zp[0];
            zx1 = zp[HID];
            zx2 = zp[2 * HID];
            zx3 = zp[3 * HID];
        }

        // load h_{t-1} into SMEM (512 threads x 1 float4)
        const float4* hprev4 = (t == 0) ? (const float4*)hidden0
                                        : (const float4*)(g_hs + (size_t)(t - 1) * HID);
        h4s[tid] = hprev4[tid];
        __syncthreads();

        // matvec: 4 gate rows of unit w; h float4 loaded once, reused 4x
        float a0 = 0.f, a1 = 0.f, a2 = 0.f, a3 = 0.f;
#pragma unroll
        for (int i = 0; i < 16; ++i) {
            int i4 = i * 32 + lane;
            float4 w2 = __ldg(w2p + i4);
            float4 w1 = g1_smem ? w1p[i4] : __ldg(w1p + i4);
            float4 w0 = w0p[i4];
            float4 w3 = w3r[i];
            float4 hv = h4[i4];
            a0 += w0.x * hv.x + w0.y * hv.y + w0.z * hv.z + w0.w * hv.w;
            a1 += w1.x * hv.x + w1.y * hv.y + w1.z * hv.z + w1.w * hv.w;
            a2 += w2.x * hv.x + w2.y * hv.y + w2.z * hv.z + w2.w * hv.w;
            a3 += w3.x * hv.x + w3.y * hv.y + w3.z * hv.z + w3.w * hv.w;
        }
        // warp reduce
#pragma unroll
        for (int off = 16; off; off >>= 1) {
            a0 += __shfl_down_sync(0xffffffffu, a0, off);
            a1 += __shfl_down_sync(0xffffffffu, a1, off);
            a2 += __shfl_down_sync(0xffffffffu, a2, off);
            a3 += __shfl_down_sync(0xffffffffu, a3, off);
        }

        // lane 0: gate math, cell update (c lives in register), h store
        if (lane == 0) {
            float zf = a0 + zx0;
            float zi = a1 + zx1;
            float zo = a2 + zx2;
            float zc = a3 + zx3;
            float f  = 1.0f / (1.0f + expf(-zf));
            float i_ = 1.0f / (1.0f + expf(-zi));
            float o_ = 1.0f / (1.0f + expf(-zo));
            float gg = tanhf(zc);
            c = f * c + i_ * gg;
            float hn = o_ * tanhf(c);
            g_hs[(size_t)t * HID + hid0 + w] = hn;
            if (t == TT - 1) {
                dout[(size_t)TT * NCH + hid0 + w] = hn;          // h_fin
                dout[(size_t)TT * NCH + HID + hid0 + w] = c;     // c_fin
            }
        }
        __syncthreads();

        // grid barrier (128 CTAs co-resident, 1/SM)
        if (tid == 0) {
            __threadfence();
            asm volatile("red.release.gpu.global.add.u32 [%0], %1;"
                         :: "l"(&g_bar), "r"(1u) : "memory");
            unsigned target = (unsigned)(t + 1) * gridDim.x;
            while (ldacq(&g_bar) < target) { }
        }
        __syncthreads();
    }
}

// ---------------------------------------------------------------------------
// K3: out[t][n] = hs[t] @ Wout + bout.  M=4096, N=256, K=2048
// ---------------------------------------------------------------------------
__global__ __launch_bounds__(256) void out_gemm_kernel(
    const float* __restrict__ Wout, const float* __restrict__ bout,
    float* __restrict__ dout)
{
    __shared__ float As[64][17];
    __shared__ float Bs[16][64];

    int m0 = blockIdx.x * 64;
    int n0 = blockIdx.y * 64;
    int tid = threadIdx.x;
    int tx = tid & 15, ty = tid >> 4;

    float acc[4][4] = {};
    for (int k0 = 0; k0 < HID; k0 += 16) {
        {
            int kk = tid & 15;
            int mmb = tid >> 4;
#pragma unroll
            for (int r = 0; r < 4; ++r) {
                int mm = mmb + r * 16;
                As[mm][kk] = g_hs[(size_t)(m0 + mm) * HID + k0 + kk];
            }
        }
        {
            int nn = tid & 63;
            int kkb = tid >> 6;
#pragma unroll
            for (int r = 0; r < 4; ++r) {
                int kk = kkb + r * 4;
                Bs[kk][nn] = Wout[(size_t)(k0 + kk) * NCH + n0 + nn];
            }
        }
        __syncthreads();
#pragma unroll
        for (int kk = 0; kk < 16; ++kk) {
            float a[4];
#pragma unroll
            for (int i = 0; i < 4; ++i) a[i] = As[ty * 4 + i][kk];
            float4 bv = *(const float4*)&Bs[kk][tx * 4];
            float b[4] = {bv.x, bv.y, bv.z, bv.w};
#pragma unroll
            for (int i = 0; i < 4; ++i)
#pragma unroll
                for (int j = 0; j < 4; ++j) acc[i][j] += a[i] * b[j];
        }
        __syncthreads();
    }
#pragma unroll
    for (int i = 0; i < 4; ++i) {
        int m = m0 + ty * 4 + i;
#pragma unroll
        for (int j = 0; j < 4; ++j) {
            int n = n0 + tx * 4 + j;
            dout[(size_t)m * NCH + n] = acc[i][j] + bout[n];
        }
    }
}

// ---------------------------------------------------------------------------
extern "C" void kernel_launch(void* const* d_in, const int* in_sizes, int n_in,
                              void* d_out, int out_size)
{
    const int*   idx    = (const int*)d_in[0];
    const float* hidden = (const float*)d_in[1];
    const float* cell   = (const float*)d_in[2];
    const float* emb    = (const float*)d_in[3];
    const float* Wf     = (const float*)d_in[4];
    const float* bf     = (const float*)d_in[5];
    const float* Wi     = (const float*)d_in[6];
    const float* bi     = (const float*)d_in[7];
    const float* Wo     = (const float*)d_in[8];
    const float* bo     = (const float*)d_in[9];
    const float* Wc     = (const float*)d_in[10];
    const float* bc     = (const float*)d_in[11];
    const float* Wout   = (const float*)d_in[12];
    const float* bout   = (const float*)d_in[13];
    float* out = (float*)d_out;

    cudaFuncSetAttribute(lstm_seq_kernel,
                         cudaFuncAttributeMaxDynamicSharedMemorySize, SMEM_BYTES);

    bar_init_kernel<<<1, 1>>>();
    wt_transpose_kernel<<<dim3(64, 64, 4), 256>>>(Wf, Wi, Wo, Wc);
    zx_gemm_kernel<<<dim3(64, 128), 256>>>(idx, emb, Wf, Wi, Wo, Wc, bf, bi, bo, bc);
    lstm_seq_kernel<<<NCTA, THR, SMEM_BYTES>>>(hidden, cell, out);
    out_gemm_kernel<<<dim3(64, 4), 256>>>(Wout, bout, out);
}